// round 13
// baseline (speedup 1.0000x reference)
#include <cuda_runtime.h>

// GEMV: out[1, 8192] = x[1, 8192] @ W[8192, 8192] + b
// d_in[0]=x (8192 f32), d_in[1]=W (8192x8192 f32 row-major), d_in[2]=b.
//
// R12: DRAM plateau (6.2 TB/s) is confirmed config-invariant; attack the
// CTA-quantization tail instead. 2048 blocks (16 col-tiles x 128 row-splits
// of 64 rows) halve the per-CTA work quantum vs R11's 1024. R5 tried this
// and regressed ONLY because __launch_bounds__(128,12) forced a 272-block
// second wave; with a 16-CTA bound (reg cap 32 = what unroll-8 compiles to)
// all 2048 blocks are co-resident -> single wave, finer tail.
// Bias still seeded by a graph memcpy node (cheapest measured: 1.6us gap).

static constexpr int IN_LEN  = 8192;
static constexpr int OUT_LEN = 8192;

static constexpr int THREADS        = 128;
static constexpr int COLS_PER_BLOCK = THREADS * 4;               // 512
static constexpr int COL_BLOCKS     = OUT_LEN / COLS_PER_BLOCK;  // 16
static constexpr int ROWS_PER_SPLIT = 64;
static constexpr int ROW_SPLITS     = IN_LEN / ROWS_PER_SPLIT;   // 128
// grid = 16 x 128 = 2048 blocks; 148 SMs x 16 CTAs = 2368 >= 2048 -> 1 wave.

__global__ __launch_bounds__(THREADS, 16)
void dense_gemv_splitk(const float* __restrict__ x,
                       const float* __restrict__ W,
                       float* __restrict__ out) {
    const int col0 = blockIdx.x * COLS_PER_BLOCK + threadIdx.x * 4;
    const int row0 = blockIdx.y * ROWS_PER_SPLIT;

    __shared__ float xs[ROWS_PER_SPLIT];
    if (threadIdx.x < ROWS_PER_SPLIT) xs[threadIdx.x] = x[row0 + threadIdx.x];
    __syncthreads();

    const float4* __restrict__ Wp =
        reinterpret_cast<const float4*>(W + (size_t)row0 * OUT_LEN + col0);
    const size_t row_stride_v4 = OUT_LEN / 4;

    float4 acc = make_float4(0.f, 0.f, 0.f, 0.f);

    // Unroll 8 compiles to 32 regs (fits the 16-CTA bound without spills);
    // chip-wide in-flight bytes come from 64 warps/SM, not per-thread depth.
    #pragma unroll 8
    for (int i = 0; i < ROWS_PER_SPLIT; i++) {
        const float xv = xs[i];
        const float4 w = Wp[(size_t)i * row_stride_v4];
        acc.x = fmaf(xv, w.x, acc.x);
        acc.y = fmaf(xv, w.y, acc.y);
        acc.z = fmaf(xv, w.z, acc.z);
        acc.w = fmaf(xv, w.w, acc.w);
    }

    // out pre-seeded with bias by the memcpy node; 128 RED.F32 per output
    // address spread across 8192 addresses -> hidden under the HBM stream.
    atomicAdd(&out[col0 + 0], acc.x);
    atomicAdd(&out[col0 + 1], acc.y);
    atomicAdd(&out[col0 + 2], acc.z);
    atomicAdd(&out[col0 + 3], acc.w);
}

extern "C" void kernel_launch(void* const* d_in, const int* in_sizes, int n_in,
                              void* d_out, int out_size) {
    const float* x = (const float*)d_in[0];
    const float* W = (const float*)d_in[1];
    const float* b = (const float*)d_in[2];
    float* out = (float*)d_out;

    // Seed out with the bias (graph memcpy node, d2d, capture-legal).
    cudaMemcpyAsync(out, b, OUT_LEN * sizeof(float), cudaMemcpyDeviceToDevice);

    dim3 grid(COL_BLOCKS, ROW_SPLITS);
    dense_gemv_splitk<<<grid, THREADS>>>(x, W, out);
}

// round 14
// speedup vs baseline: 1.2050x; 1.2050x over previous
#include <cuda_runtime.h>

// GEMV: out[1, 8192] = x[1, 8192] @ W[8192, 8192] + b
// d_in[0]=x (8192 f32), d_in[1]=W (8192x8192 f32 row-major), d_in[2]=b.
//
// R14 (convergence): compose the two best-measured pieces.
//  - Kernel body = R7's (fastest measured: 43.9us): 1024 blocks (16 col-
//    tiles x 64 row-splits), unroll 16, 7-CTA bound (72 regs), plain LDG
//    (__ldcs measured neutral; 2048-block grids measured strictly worse).
//  - Bias = R11's graph memcpy node (cheapest measured pre-seed: 1.6us gap),
//    removing R7's per-block bias branch.
// Established: 6.2 TB/s (78% of spec) is the config-invariant read ceiling;
// memory-path tuning is closed.

static constexpr int IN_LEN  = 8192;
static constexpr int OUT_LEN = 8192;

static constexpr int THREADS        = 128;
static constexpr int COLS_PER_BLOCK = THREADS * 4;               // 512
static constexpr int COL_BLOCKS     = OUT_LEN / COLS_PER_BLOCK;  // 16
static constexpr int ROWS_PER_SPLIT = 128;
static constexpr int ROW_SPLITS     = IN_LEN / ROWS_PER_SPLIT;   // 64
// grid = 16 x 64 = 1024 blocks -> single wave, best measured geometry.

__global__ __launch_bounds__(THREADS, 7)
void dense_gemv_splitk(const float* __restrict__ x,
                       const float* __restrict__ W,
                       float* __restrict__ out) {
    const int col0 = blockIdx.x * COLS_PER_BLOCK + threadIdx.x * 4;
    const int row0 = blockIdx.y * ROWS_PER_SPLIT;

    __shared__ float xs[ROWS_PER_SPLIT];
    xs[threadIdx.x] = x[row0 + threadIdx.x];
    __syncthreads();

    const float4* __restrict__ Wp =
        reinterpret_cast<const float4*>(W + (size_t)row0 * OUT_LEN + col0);
    const size_t row_stride_v4 = OUT_LEN / 4;

    float4 acc = make_float4(0.f, 0.f, 0.f, 0.f);

    // Deep unroll: ~16 independent LDG.128 in flight per thread under the
    // 7-CTA register budget (72 regs). Fastest measured body.
    #pragma unroll 16
    for (int i = 0; i < ROWS_PER_SPLIT; i++) {
        const float xv = xs[i];
        const float4 w = Wp[(size_t)i * row_stride_v4];
        acc.x = fmaf(xv, w.x, acc.x);
        acc.y = fmaf(xv, w.y, acc.y);
        acc.z = fmaf(xv, w.z, acc.z);
        acc.w = fmaf(xv, w.w, acc.w);
    }

    // out pre-seeded with bias by the memcpy node; 64 RED.F32 per output
    // address spread across 8192 addresses -> hidden under the HBM stream.
    atomicAdd(&out[col0 + 0], acc.x);
    atomicAdd(&out[col0 + 1], acc.y);
    atomicAdd(&out[col0 + 2], acc.z);
    atomicAdd(&out[col0 + 3], acc.w);
}

extern "C" void kernel_launch(void* const* d_in, const int* in_sizes, int n_in,
                              void* d_out, int out_size) {
    const float* x = (const float*)d_in[0];
    const float* W = (const float*)d_in[1];
    const float* b = (const float*)d_in[2];
    float* out = (float*)d_out;

    // Seed out with the bias (graph memcpy node, d2d, capture-legal).
    cudaMemcpyAsync(out, b, OUT_LEN * sizeof(float), cudaMemcpyDeviceToDevice);

    dim3 grid(COL_BLOCKS, ROW_SPLITS);
    dense_gemv_splitk<<<grid, THREADS>>>(x, W, out);
}

// round 15
// speedup vs baseline: 1.2404x; 1.0294x over previous
#include <cuda_runtime.h>

// GEMV: out[1, 8192] = x[1, 8192] @ W[8192, 8192] + b
// d_in[0]=x (8192 f32), d_in[1]=W (8192x8192 f32 row-major), d_in[2]=b.
//
// R15: kernel body is converged (44.0us vs 41.3us stream floor at the
// config-invariant 6.2TB/s ceiling). Remaining addressable time is the
// 1.6-3.1us inter-node serialization gap between the bias seed and the
// gemv. Fix via Programmatic Dependent Launch: gemv is launched with the
// programmatic-serialization attribute and only calls
// cudaGridDependencySynchronize() AFTER the 40us W-streaming loop, right
// before its atomicAdd epilogue -- the bias kernel (~2us) completes fully
// underneath the load phase.

static constexpr int IN_LEN  = 8192;
static constexpr int OUT_LEN = 8192;

static constexpr int THREADS        = 128;
static constexpr int COLS_PER_BLOCK = THREADS * 4;               // 512
static constexpr int COL_BLOCKS     = OUT_LEN / COLS_PER_BLOCK;  // 16
static constexpr int ROWS_PER_SPLIT = 128;
static constexpr int ROW_SPLITS     = IN_LEN / ROWS_PER_SPLIT;   // 64
// grid = 16 x 64 = 1024 blocks -> single wave, best measured geometry.

__global__ void dense_init_bias(const float* __restrict__ b,
                                float* __restrict__ out) {
    int j = blockIdx.x * blockDim.x + threadIdx.x;
    out[j] = b[j];
    // Allow the dependent gemv grid to launch immediately.
    cudaTriggerProgrammaticLaunchCompletion();
}

__global__ __launch_bounds__(THREADS, 7)
void dense_gemv_splitk(const float* __restrict__ x,
                       const float* __restrict__ W,
                       float* __restrict__ out) {
    const int col0 = blockIdx.x * COLS_PER_BLOCK + threadIdx.x * 4;
    const int row0 = blockIdx.y * ROWS_PER_SPLIT;

    __shared__ float xs[ROWS_PER_SPLIT];
    xs[threadIdx.x] = x[row0 + threadIdx.x];
    __syncthreads();

    const float4* __restrict__ Wp =
        reinterpret_cast<const float4*>(W + (size_t)row0 * OUT_LEN + col0);
    const size_t row_stride_v4 = OUT_LEN / 4;

    float4 acc = make_float4(0.f, 0.f, 0.f, 0.f);

    // Fastest measured body: ~16 independent LDG.128 in flight per thread
    // under the 7-CTA register budget (72 regs).
    #pragma unroll 16
    for (int i = 0; i < ROWS_PER_SPLIT; i++) {
        const float xv = xs[i];
        const float4 w = Wp[(size_t)i * row_stride_v4];
        acc.x = fmaf(xv, w.x, acc.x);
        acc.y = fmaf(xv, w.y, acc.y);
        acc.z = fmaf(xv, w.z, acc.z);
        acc.w = fmaf(xv, w.w, acc.w);
    }

    // Only here do we depend on the bias seed: wait for the predecessor
    // grid's completion (long since done -- it ran under the 40us stream).
    cudaGridDependencySynchronize();

    atomicAdd(&out[col0 + 0], acc.x);
    atomicAdd(&out[col0 + 1], acc.y);
    atomicAdd(&out[col0 + 2], acc.z);
    atomicAdd(&out[col0 + 3], acc.w);
}

extern "C" void kernel_launch(void* const* d_in, const int* in_sizes, int n_in,
                              void* d_out, int out_size) {
    const float* x = (const float*)d_in[0];
    const float* W = (const float*)d_in[1];
    const float* b = (const float*)d_in[2];
    float* out = (float*)d_out;

    dense_init_bias<<<OUT_LEN / 256, 256>>>(b, out);

    cudaLaunchConfig_t cfg = {};
    cfg.gridDim  = dim3(COL_BLOCKS, ROW_SPLITS, 1);
    cfg.blockDim = dim3(THREADS, 1, 1);
    cfg.dynamicSmemBytes = 0;
    cfg.stream = 0;
    cudaLaunchAttribute attr[1];
    attr[0].id = cudaLaunchAttributeProgrammaticStreamSerialization;
    attr[0].val.programmaticStreamSerializationAllowed = 1;
    cfg.attrs = attr;
    cfg.numAttrs = 1;
    cudaLaunchKernelEx(&cfg, dense_gemv_splitk, x, W, out);
}

// round 17
// speedup vs baseline: 1.3051x; 1.0522x over previous
#include <cuda_runtime.h>

// GEMV: out[1, 8192] = x[1, 8192] @ W[8192, 8192] + b
// d_in[0]=x (8192 f32), d_in[1]=W (8192x8192 f32 row-major), d_in[2]=b.
//
// R16 (final polish): R15's PDL structure, but the programmatic-launch
// trigger is issued as the FIRST instruction of the bias-seed kernel, so
// the gemv's launch overlaps init's execution instead of following it.
// Safe because cudaGridDependencySynchronize() in the gemv (placed after
// the ~40us W-stream, right before the atomic epilogue) still waits for the
// init grid's FULL completion -- the trigger only releases the launch.
//
// Frozen at measured optima: 16x64=1024 blocks (single wave; 2048 strictly
// worse), unroll 16 @ 7-CTA bound (72 regs; 4-deep/32-reg identical DRAM%),
// plain LDG (__ldcs neutral), split-K RED.F32 into bias-seeded out (fence-
// based single-kernel combine measured 2.4us worse). Kernel runs at
// 6.28 TB/s = 78.5% of spec, the config-invariant read ceiling.

static constexpr int IN_LEN  = 8192;
static constexpr int OUT_LEN = 8192;

static constexpr int THREADS        = 128;
static constexpr int COLS_PER_BLOCK = THREADS * 4;               // 512
static constexpr int COL_BLOCKS     = OUT_LEN / COLS_PER_BLOCK;  // 16
static constexpr int ROWS_PER_SPLIT = 128;
static constexpr int ROW_SPLITS     = IN_LEN / ROWS_PER_SPLIT;   // 64
// grid = 16 x 64 = 1024 blocks -> single wave, best measured geometry.

__global__ void dense_init_bias(const float* __restrict__ b,
                                float* __restrict__ out) {
    // Release the dependent gemv launch immediately; our stores are covered
    // by its cudaGridDependencySynchronize() (full-completion wait).
    cudaTriggerProgrammaticLaunchCompletion();
    int j = blockIdx.x * blockDim.x + threadIdx.x;
    out[j] = b[j];
}

__global__ __launch_bounds__(THREADS, 7)
void dense_gemv_splitk(const float* __restrict__ x,
                       const float* __restrict__ W,
                       float* __restrict__ out) {
    const int col0 = blockIdx.x * COLS_PER_BLOCK + threadIdx.x * 4;
    const int row0 = blockIdx.y * ROWS_PER_SPLIT;

    __shared__ float xs[ROWS_PER_SPLIT];
    xs[threadIdx.x] = x[row0 + threadIdx.x];
    __syncthreads();

    const float4* __restrict__ Wp =
        reinterpret_cast<const float4*>(W + (size_t)row0 * OUT_LEN + col0);
    const size_t row_stride_v4 = OUT_LEN / 4;

    float4 acc = make_float4(0.f, 0.f, 0.f, 0.f);

    // Fastest measured body: ~16 independent LDG.128 in flight per thread
    // under the 7-CTA register budget.
    #pragma unroll 16
    for (int i = 0; i < ROWS_PER_SPLIT; i++) {
        const float xv = xs[i];
        const float4 w = Wp[(size_t)i * row_stride_v4];
        acc.x = fmaf(xv, w.x, acc.x);
        acc.y = fmaf(xv, w.y, acc.y);
        acc.z = fmaf(xv, w.z, acc.z);
        acc.w = fmaf(xv, w.w, acc.w);
    }

    // First (and only) dependence on the bias seed: wait for the init
    // grid's completion -- long since done under the 40us W stream.
    cudaGridDependencySynchronize();

    atomicAdd(&out[col0 + 0], acc.x);
    atomicAdd(&out[col0 + 1], acc.y);
    atomicAdd(&out[col0 + 2], acc.z);
    atomicAdd(&out[col0 + 3], acc.w);
}

extern "C" void kernel_launch(void* const* d_in, const int* in_sizes, int n_in,
                              void* d_out, int out_size) {
    const float* x = (const float*)d_in[0];
    const float* W = (const float*)d_in[1];
    const float* b = (const float*)d_in[2];
    float* out = (float*)d_out;

    dense_init_bias<<<OUT_LEN / 256, 256>>>(b, out);

    cudaLaunchConfig_t cfg = {};
    cfg.gridDim  = dim3(COL_BLOCKS, ROW_SPLITS, 1);
    cfg.blockDim = dim3(THREADS, 1, 1);
    cfg.dynamicSmemBytes = 0;
    cfg.stream = 0;
    cudaLaunchAttribute attr[1];
    attr[0].id = cudaLaunchAttributeProgrammaticStreamSerialization;
    attr[0].val.programmaticStreamSerializationAllowed = 1;
    cfg.attrs = attr;
    cfg.numAttrs = 1;
    cudaLaunchKernelEx(&cfg, dense_gemv_splitk, x, W, out);
}